// round 15
// baseline (speedup 1.0000x reference)
#include <cuda_runtime.h>
#include <cstdint>

// x: [B=16, T=4096, D=1024] f32, out: [B, D] = sum over T.
// Bulk-async pipeline: the DRAM request stream has been the binder (every
// LDG-based variant pins at 5.6-5.8 TB/s regardless of occ/MLP/balance).
// cp.async.bulk issues ONE 16KB contiguous transfer per request instead of
// 512B warp-slices, improving HBM row-buffer locality.
//   grid 592 = 4*148, static 111/110-row partition (validated R13/14).
//   Per CTA: 2 x 16KB SMEM buffers, elected-thread cp.async.bulk +
//   mbarrier expect_tx, 256 threads acquire-wait then reduce the 4-row
//   tile from SMEM (warp reads 512B contiguous -> conflict-free).
//   Tail: validated ticket protocol (fence -> syncthreads -> atomic).

#define B_DIM 16
#define T_DIM 4096
#define D_DIM 1024
#define D4 (D_DIM / 4)          // 256 float4 per row
#define BPB 37
#define HEAVY 26                // 26 x 111 + 11 x 110 = 4096
#define GRID (B_DIM * BPB)      // 592 = 4 * 148
#define TILE_ROWS 4
#define TILE_BYTES (TILE_ROWS * D_DIM * 4)   // 16384
#define NBUF 2

__device__ float g_partial[GRID * D_DIM];
__device__ int g_count[B_DIM];

__device__ __forceinline__ uint32_t smem_u32(const void* p) {
    uint32_t a;
    asm("{ .reg .u64 t; cvta.to.shared.u64 t, %1; cvt.u32.u64 %0, t; }"
        : "=r"(a) : "l"(p));
    return a;
}

__device__ __forceinline__ void mbar_init(uint32_t bar, uint32_t cnt) {
    asm volatile("mbarrier.init.shared.b64 [%0], %1;" :: "r"(bar), "r"(cnt) : "memory");
}

__device__ __forceinline__ void bulk_issue(uint32_t bar, uint32_t dst,
                                           const void* src, uint32_t bytes) {
    asm volatile("mbarrier.arrive.expect_tx.shared.b64 _, [%0], %1;"
                 :: "r"(bar), "r"(bytes) : "memory");
    asm volatile("cp.async.bulk.shared::cta.global.mbarrier::complete_tx::bytes "
                 "[%0], [%1], %2, [%3];"
                 :: "r"(dst), "l"(src), "r"(bytes), "r"(bar) : "memory");
}

__device__ __forceinline__ void mbar_wait(uint32_t bar, uint32_t parity) {
    asm volatile(
        "{\n\t"
        ".reg .pred P;\n\t"
        "WL_%=:\n\t"
        "mbarrier.try_wait.parity.acquire.cta.shared::cta.b64 P, [%0], %1, 0x989680;\n\t"
        "@P bra.uni WD_%=;\n\t"
        "bra.uni WL_%=;\n\t"
        "WD_%=:\n\t"
        "}" :: "r"(bar), "r"(parity) : "memory");
}

template <int NROWS>
__device__ __forceinline__ float4 stream_bulk(
    const float* xrow0, float4* s_buf, uint32_t buf_a0, uint32_t buf_a1,
    uint32_t bar_a0, uint32_t bar_a1, int tid)
{
    constexpr int NSTAGES = (NROWS + TILE_ROWS - 1) / TILE_ROWS;
    constexpr int LAST_ROWS = NROWS - (NSTAGES - 1) * TILE_ROWS;

    const uint32_t buf_addr[2] = {buf_a0, buf_a1};
    const uint32_t bar_addr[2] = {bar_a0, bar_a1};

    // Prologue: fill both buffers.
    if (tid == 0) {
        bulk_issue(bar_addr[0], buf_addr[0], xrow0, TILE_BYTES);
        if (NSTAGES > 1) {
            uint32_t by1 = (NSTAGES == 2) ? LAST_ROWS * D_DIM * 4 : TILE_BYTES;
            bulk_issue(bar_addr[1], buf_addr[1],
                       xrow0 + (size_t)TILE_ROWS * D_DIM, by1);
        }
    }

    float4 acc = make_float4(0.f, 0.f, 0.f, 0.f);

    for (int s = 0; s < NSTAGES; ++s) {
        const int bsel = s & 1;
        mbar_wait(bar_addr[bsel], (s >> 1) & 1);

        const int rows = (s == NSTAGES - 1) ? LAST_ROWS : TILE_ROWS;
        const float4* tb = s_buf + bsel * (TILE_ROWS * D4);
        #pragma unroll
        for (int r = 0; r < TILE_ROWS; ++r) {
            if (r < rows) {
                float4 v = tb[r * D4 + tid];
                acc.x += v.x; acc.y += v.y; acc.z += v.z; acc.w += v.w;
            }
        }
        __syncthreads();   // everyone done with this buffer before refill

        const int ns = s + NBUF;
        if (ns < NSTAGES && tid == 0) {
            uint32_t by = (ns == NSTAGES - 1) ? LAST_ROWS * D_DIM * 4 : TILE_BYTES;
            bulk_issue(bar_addr[bsel], buf_addr[bsel],
                       xrow0 + (size_t)ns * TILE_ROWS * D_DIM, by);
        }
    }
    return acc;
}

__global__ __launch_bounds__(256, 4)
void sum_bulk(const float* __restrict__ x, float* __restrict__ out) {
    __shared__ float4 s_buf[NBUF][TILE_ROWS * D4];   // 32 KB
    __shared__ alignas(8) uint64_t s_mbar[NBUF];
    __shared__ int s_is_last;

    const int j   = blockIdx.x;        // 0..591
    const int tid = threadIdx.x;       // 0..255
    const int b   = j / BPB;
    const int w   = j - b * BPB;

    const uint32_t bar0 = smem_u32(&s_mbar[0]);
    const uint32_t bar1 = smem_u32(&s_mbar[1]);
    const uint32_t buf0 = smem_u32(&s_buf[0][0]);
    const uint32_t buf1 = smem_u32(&s_buf[1][0]);

    if (tid == 0) { mbar_init(bar0, 1); mbar_init(bar1, 1); }
    __syncthreads();

    const int rstart = (w < HEAVY) ? w * 111 : HEAVY * 111 + (w - HEAVY) * 110;
    const float* xrow0 = x + ((size_t)b * T_DIM + rstart) * D_DIM;

    float4 acc = (w < HEAVY)
        ? stream_bulk<111>(xrow0, &s_buf[0][0], buf0, buf1, bar0, bar1, tid)
        : stream_bulk<110>(xrow0, &s_buf[0][0], buf0, buf1, bar0, bar1, tid);

    reinterpret_cast<float4*>(g_partial)[(size_t)j * D4 + tid] = acc;

    // Release: own-store fence, block rendezvous, tid0 takes the ticket.
    __threadfence();
    __syncthreads();
    if (tid == 0) {
        int ticket = atomicAdd(&g_count[b], 1);
        s_is_last = (ticket == BPB - 1);
    }
    __syncthreads();

    if (s_is_last) {
        __threadfence();   // acquire
        const float4* base =
            reinterpret_cast<const float4*>(g_partial) + (size_t)b * BPB * D4;
        float4 rsum = make_float4(0.f, 0.f, 0.f, 0.f);
        #pragma unroll
        for (int k = 0; k < BPB; ++k) {
            float4 v = base[(size_t)k * D4 + tid];
            rsum.x += v.x; rsum.y += v.y; rsum.z += v.z; rsum.w += v.w;
        }
        reinterpret_cast<float4*>(out)[(size_t)b * D4 + tid] = rsum;
        __syncthreads();
        if (tid == 0) g_count[b] = 0;   // graph-replay safe
    }
}

extern "C" void kernel_launch(void* const* d_in, const int* in_sizes, int n_in,
                              void* d_out, int out_size) {
    const float* x = (const float*)d_in[0];
    float* out = (float*)d_out;
    sum_bulk<<<GRID, 256>>>(x, out);
}